// round 14
// baseline (speedup 1.0000x reference)
#include <cuda_runtime.h>
#include <cuda_bf16.h>
#include <cstdint>

#define B_   32
#define C_   384
#define HW_  4096
#define M_   64
#define R_   16

typedef unsigned long long ull;

// scratch: W = U*Vw split to bf16 hi/lo, bL = U*Vb
__device__ __nv_bfloat16 g_Whi[M_ * C_];
__device__ __nv_bfloat16 g_Wlo[M_ * C_];
__device__ float         g_bL[M_];

// ---------------- common helpers ----------------
__device__ __forceinline__ uint32_t smem_u32(const void* p) {
    uint32_t a;
    asm("{ .reg .u64 t; cvta.to.shared.u64 t, %1; cvt.u32.u64 %0, t; }"
        : "=r"(a) : "l"(p));
    return a;
}
__device__ __forceinline__ uint32_t sw128(uint32_t off) {
    return off ^ ((off >> 3) & 0x70);
}
__device__ __forceinline__ void ldsm4(uint32_t* r, uint32_t addr) {
    asm volatile("ldmatrix.sync.aligned.m8n8.x4.shared.b16 {%0,%1,%2,%3}, [%4];"
        : "=r"(r[0]), "=r"(r[1]), "=r"(r[2]), "=r"(r[3]) : "r"(addr));
}
__device__ __forceinline__ void mma_bf16(float* d, const uint32_t* a,
                                         const uint32_t* b) {
    asm volatile(
        "mma.sync.aligned.m16n8k16.row.col.f32.bf16.bf16.f32 "
        "{%0,%1,%2,%3}, {%4,%5,%6,%7}, {%8,%9}, {%0,%1,%2,%3};"
        : "+f"(d[0]), "+f"(d[1]), "+f"(d[2]), "+f"(d[3])
        : "r"(a[0]), "r"(a[1]), "r"(a[2]), "r"(a[3]), "r"(b[0]), "r"(b[1]));
}

// ---------------- kernel 0: W = U Vw (fp32), split bf16; bL = U Vb --------
// grid 24 x 128. g = m*48 + strip; each thread: 8 c-values of one m-row.
__global__ void k_w(const float* __restrict__ U, const float* __restrict__ Vw,
                    const float* __restrict__ Vb)
{
    int g = blockIdx.x * 128 + threadIdx.x;       // 0..3071
    int m = g / 48;
    int c0 = (g % 48) * 8;

    float u[R_];
#pragma unroll
    for (int r = 0; r < R_; r++) u[r] = U[m * R_ + r];

#pragma unroll
    for (int j = 0; j < 8; j++) {
        int c = c0 + j;
        float acc = 0.0f;
#pragma unroll
        for (int r = 0; r < R_; r++) acc += u[r] * Vw[r * C_ + c];
        __nv_bfloat16 h = __float2bfloat16_rn(acc);
        float lo = acc - __bfloat162float(h);
        g_Whi[m * C_ + c] = h;
        g_Wlo[m * C_ + c] = __float2bfloat16_rn(lo);
    }

    if (g < M_) {
        float acc = 0.0f;
#pragma unroll
        for (int r = 0; r < R_; r++) acc += U[g * R_ + r] * Vb[r];
        g_bL[g] = acc;
    }
}

// ---------------- kernel 1: L = W x + bL ; S = softmax_M(L) ---------------
// grid (16 n-tiles, 32 b), 256 threads (8 warps x 32 n each).
// W hi/lo resident in smem (padded rows, 784B); x staged transposed per
// 64-c chunk (SW128). mma bf16 3-term. Softmax over m via shfl. Zeroes T.

#define NT    256                     // n per block
#define CCH   64                      // c per chunk
#define NCH   (C_ / CCH)              // 6

// smem byte offsets
#define SW_HI 0                       // W hi: 64 rows x 784B = 50176
#define SW_LO 50176
#define SX_HI 100352                  // x tile: 256 rows x 128B = 32768
#define SX_LO 133120
#define SBL   165888                  // 64 floats
#define SMEM_LOG 166144

__global__ __launch_bounds__(256, 1) void k_logits(
    const float* __restrict__ x, float* __restrict__ S, float* __restrict__ T)
{
    extern __shared__ char smem[];
    const uint32_t sb = smem_u32(smem);
    const int tid = threadIdx.x;
    const int w   = tid >> 5;
    const int l   = tid & 31;
    const int b   = blockIdx.y;
    const int n0  = blockIdx.x * NT;

    // fused zero of T: 512 blocks x 256 thr x 6 floats = 786432
    {
        int gt = (blockIdx.y * gridDim.x + blockIdx.x) * 256 + tid;
        float2* tz = (float2*)T + (size_t)gt * 3;
        float2 z = make_float2(0.0f, 0.0f);
        tz[0] = z; tz[1] = z; tz[2] = z;
    }

    // load W hi/lo into padded smem (row stride 392 bf16 = 784B)
    {
        __nv_bfloat16* whi = (__nv_bfloat16*)(smem + SW_HI);
        __nv_bfloat16* wlo = (__nv_bfloat16*)(smem + SW_LO);
        for (int i = tid; i < M_ * C_; i += 256) {
            int r = i / C_, c = i % C_;
            int d = r * 392 + c;
            whi[d] = g_Whi[i];
            wlo[d] = g_Wlo[i];
        }
    }
    if (tid < M_) ((float*)(smem + SBL))[tid] = g_bL[tid];

    // lane addressing
    const int arow = l & 15;
    const int acol = (l >> 4) << 4;               // bytes
    const int nrow = (l & 7) + ((l >> 4) << 3);
    const int bcol = ((l >> 3) & 1) << 4;         // bytes

    float acc[4][4][4];                           // [mt][j(n8)][reg]
#pragma unroll
    for (int mt = 0; mt < 4; mt++)
#pragma unroll
        for (int j = 0; j < 4; j++)
#pragma unroll
            for (int q = 0; q < 4; q++) acc[mt][j][q] = 0.0f;

    __syncthreads();

    const float* xb = x + (size_t)b * C_ * HW_ + n0 + tid;  // row n = tid

    for (int ch = 0; ch < NCH; ch++) {
        // stage x[chunk c's][256 n] transposed -> smem [n][c], SW128
        __syncthreads();
        {
            const float* xp = xb + (size_t)(ch * CCH) * HW_;
            const uint32_t rowb = (uint32_t)tid * 128;
#pragma unroll 8
            for (int cp = 0; cp < 32; cp++) {
                float v0 = xp[(size_t)(2 * cp) * HW_];
                float v1 = xp[(size_t)(2 * cp + 1) * HW_];
                __nv_bfloat162 h = __floats2bfloat162_rn(v0, v1);
                float r0 = v0 - __bfloat162float(h.x);
                float r1 = v1 - __bfloat162float(h.y);
                __nv_bfloat162 lo = __floats2bfloat162_rn(r0, r1);
                uint32_t sw = sw128(rowb + 4 * cp);
                *(uint32_t*)(smem + SX_HI + sw) = *(uint32_t*)&h;
                *(uint32_t*)(smem + SX_LO + sw) = *(uint32_t*)&lo;
            }
        }
        __syncthreads();

        // compute: 4 k-steps of 16 within chunk
#pragma unroll
        for (int s = 0; s < 4; s++) {
            uint32_t ah[4][4], al[4][4];
            const uint32_t acb = (uint32_t)(ch * 128 + 32 * s) + acol;
#pragma unroll
            for (int mt = 0; mt < 4; mt++) {
                uint32_t aa = (uint32_t)(16 * mt + arow) * 784 + acb;
                ldsm4(ah[mt], sb + SW_HI + aa);
                ldsm4(al[mt], sb + SW_LO + aa);
            }
            uint32_t bh[2][4], bl[2][4];
#pragma unroll
            for (int h = 0; h < 2; h++) {
                uint32_t ba = sw128((uint32_t)(32 * w + 16 * h + nrow) * 128
                                    + 32 * s + bcol);
                ldsm4(bh[h], sb + SX_HI + ba);
                ldsm4(bl[h], sb + SX_LO + ba);
            }
#pragma unroll
            for (int mt = 0; mt < 4; mt++)
#pragma unroll
                for (int h = 0; h < 2; h++) {
                    mma_bf16(acc[mt][2 * h],     ah[mt], bh[h]);
                    mma_bf16(acc[mt][2 * h],     ah[mt], bl[h]);
                    mma_bf16(acc[mt][2 * h],     al[mt], bh[h]);
                    mma_bf16(acc[mt][2 * h + 1], ah[mt], bh[h] + 2);
                    mma_bf16(acc[mt][2 * h + 1], ah[mt], bl[h] + 2);
                    mma_bf16(acc[mt][2 * h + 1], al[mt], bh[h] + 2);
                }
        }
    }

    // bias
    const int g  = l >> 2;
    const int tg = l & 3;
    {
        const float* sbl = (const float*)(smem + SBL);
#pragma unroll
        for (int mt = 0; mt < 4; mt++) {
            float b0 = sbl[16 * mt + g];
            float b1 = sbl[16 * mt + 8 + g];
#pragma unroll
            for (int j = 0; j < 4; j++) {
                acc[mt][j][0] += b0; acc[mt][j][1] += b0;
                acc[mt][j][2] += b1; acc[mt][j][3] += b1;
            }
        }
    }

    // softmax over m=64: 8 local + shfl over g-groups (xor 4,8,16)
#pragma unroll
    for (int j = 0; j < 4; j++)
#pragma unroll
        for (int col = 0; col < 2; col++) {
            float mx = -1e30f;
#pragma unroll
            for (int mt = 0; mt < 4; mt++)
                mx = fmaxf(mx, fmaxf(acc[mt][j][col], acc[mt][j][col + 2]));
            mx = fmaxf(mx, __shfl_xor_sync(0xffffffffu, mx, 4));
            mx = fmaxf(mx, __shfl_xor_sync(0xffffffffu, mx, 8));
            mx = fmaxf(mx, __shfl_xor_sync(0xffffffffu, mx, 16));
            float sum = 0.0f;
#pragma unroll
            for (int mt = 0; mt < 4; mt++) {
                float e0 = __expf(acc[mt][j][col] - mx);
                float e1 = __expf(acc[mt][j][col + 2] - mx);
                acc[mt][j][col] = e0; acc[mt][j][col + 2] = e1;
                sum += e0 + e1;
            }
            sum += __shfl_xor_sync(0xffffffffu, sum, 4);
            sum += __shfl_xor_sync(0xffffffffu, sum, 8);
            sum += __shfl_xor_sync(0xffffffffu, sum, 16);
            float inv = 1.0f / sum;
#pragma unroll
            for (int mt = 0; mt < 4; mt++) {
                acc[mt][j][col] *= inv; acc[mt][j][col + 2] *= inv;
            }
        }

    // store S[b][m][n]
    float* sp = S + (size_t)b * M_ * HW_ + n0 + 32 * w + 2 * tg;
#pragma unroll
    for (int mt = 0; mt < 4; mt++)
#pragma unroll
        for (int j = 0; j < 4; j++) {
            int r0 = 16 * mt + g;
            *(float2*)(sp + (size_t)r0 * HW_ + 8 * j) =
                make_float2(acc[mt][j][0], acc[mt][j][1]);
            *(float2*)(sp + (size_t)(r0 + 8) * HW_ + 8 * j) =
                make_float2(acc[mt][j][2], acc[mt][j][3]);
        }
}

// ================= pool kernel: warp-level bf16 mma.sync =================
// (round-9 proven version, unchanged)
// K-split 3 (grid.z): chunks 22/21/21, atomicAdd into zeroed T.

#define CTILE  128
#define KC     64

#define SM_AHI 0
#define SM_ALO 16384
#define SM_BHI 32768
#define SM_BLO 40960
#define SM_TOTAL 49152

__global__ __launch_bounds__(256, 1) void k_pool_mma(
    const float* __restrict__ x, const float* __restrict__ S,
    float* __restrict__ T)
{
    extern __shared__ char smem[];
    const uint32_t sb = smem_u32(smem);
    const int tid = threadIdx.x;
    const int w   = tid >> 5;
    const int l   = tid & 31;
    const int c0  = blockIdx.x * CTILE;
    const int b   = blockIdx.y;
    const int ks  = blockIdx.z;                   // 0..2

    const int start = (ks == 0) ? 0 : (22 + 21 * (ks - 1));
    const int cnt   = (ks == 0) ? 22 : 21;

    const float* xb = x + ((size_t)b * C_ + c0) * HW_;
    const float* Sb = S + (size_t)b * M_ * HW_;

    const int cp = tid & 31;
    const int r0 = tid >> 5;

    const int arow = 16 * w + (l & 15);
    const int acol = (l >> 4) * 16;
    const int nrow = (l & 7) + ((l >> 4) << 3);
    const int bcol = ((l >> 3) & 1) * 16;

    float acc[8][4];
#pragma unroll
    for (int j = 0; j < 8; j++)
#pragma unroll
        for (int q = 0; q < 4; q++) acc[j][q] = 0.0f;

    float2 av[16], bv[8];
    {
        const int k0 = start * KC;
#pragma unroll
        for (int i = 0; i < 16; i++)
            av[i] = *(const float2*)(xb + (size_t)(r0 + 8 * i) * HW_ + k0 + 2 * cp);
#pragma unroll
        for (int i = 0; i < 8; i++)
            bv[i] = *(const float2*)(Sb + (size_t)(r0 + 8 * i) * HW_ + k0 + 2 * cp);
    }

    for (int ci = 0; ci < cnt; ci++) {
#pragma unroll
        for (int i = 0; i < 16; i++) {
            uint32_t sw = sw128((r0 + 8 * i) * 128 + 4 * cp);
            __nv_bfloat162 h = __floats2bfloat162_rn(av[i].x, av[i].y);
            float rx = av[i].x - __bfloat162float(h.x);
            float ry = av[i].y - __bfloat162float(h.y);
            __nv_bfloat162 lo = __floats2bfloat162_rn(rx, ry);
            *(uint32_t*)(smem + SM_AHI + sw) = *(uint32_t*)&h;
            *(uint32_t*)(smem + SM_ALO + sw) = *(uint32_t*)&lo;
        }
#pragma unroll
        for (int i = 0; i < 8; i++) {
            uint32_t sw = sw128((r0 + 8 * i) * 128 + 4 * cp);
            __nv_bfloat162 h = __floats2bfloat162_rn(bv[i].x, bv[i].y);
            float rx = bv[i].x - __bfloat162float(h.x);
            float ry = bv[i].y - __bfloat162float(h.y);
            __nv_bfloat162 lo = __floats2bfloat162_rn(rx, ry);
            *(uint32_t*)(smem + SM_BHI + sw) = *(uint32_t*)&h;
            *(uint32_t*)(smem + SM_BLO + sw) = *(uint32_t*)&lo;
        }
        __syncthreads();

        if (ci + 1 < cnt) {
            const int k1 = (start + ci + 1) * KC;
#pragma unroll
            for (int i = 0; i < 16; i++)
                av[i] = *(const float2*)(xb + (size_t)(r0 + 8 * i) * HW_ + k1 + 2 * cp);
#pragma unroll
            for (int i = 0; i < 8; i++)
                bv[i] = *(const float2*)(Sb + (size_t)(r0 + 8 * i) * HW_ + k1 + 2 * cp);
        }

#pragma unroll
        for (int s = 0; s < 4; s++) {
            uint32_t ah[4], al[4];
            uint32_t asw = sw128(arow * 128 + 32 * s + acol);
            ldsm4(ah, sb + SM_AHI + asw);
            ldsm4(al, sb + SM_ALO + asw);
#pragma unroll
            for (int jp = 0; jp < 4; jp++) {
                uint32_t bh[4], bl[4];
                uint32_t bsw = sw128((16 * jp + nrow) * 128 + 32 * s + bcol);
                ldsm4(bh, sb + SM_BHI + bsw);
                ldsm4(bl, sb + SM_BLO + bsw);
                mma_bf16(acc[2 * jp],     ah, bh);
                mma_bf16(acc[2 * jp],     ah, bl);
                mma_bf16(acc[2 * jp],     al, bh);
                mma_bf16(acc[2 * jp + 1], ah, bh + 2);
                mma_bf16(acc[2 * jp + 1], ah, bl + 2);
                mma_bf16(acc[2 * jp + 1], al, bh + 2);
            }
        }
        __syncthreads();
    }

    const int g  = l >> 2;
    const int q2 = (l & 3) * 2;
    float* tb = T + ((size_t)b * C_ + c0 + 16 * w) * M_;
#pragma unroll
    for (int j = 0; j < 8; j++) {
        atomicAdd(tb + (size_t)g * M_ + 8 * j + q2,           acc[j][0]);
        atomicAdd(tb + (size_t)g * M_ + 8 * j + q2 + 1,       acc[j][1]);
        atomicAdd(tb + (size_t)(g + 8) * M_ + 8 * j + q2,     acc[j][2]);
        atomicAdd(tb + (size_t)(g + 8) * M_ + 8 * j + q2 + 1, acc[j][3]);
    }
}

// ---------------- launch ----------------
extern "C" void kernel_launch(void* const* d_in, const int* in_sizes, int n_in,
                              void* d_out, int out_size)
{
    const float* x  = (const float*)d_in[0];
    const float* Vw = (const float*)d_in[1];
    const float* Vb = (const float*)d_in[2];
    const float* U  = (const float*)d_in[3];

    float* out = (float*)d_out;
    float* T = out;                           // [B, C, M]
    float* S = out + (size_t)B_ * C_ * M_;    // [B, M, N]

    cudaFuncSetAttribute(k_logits, cudaFuncAttributeMaxDynamicSharedMemorySize,
                         SMEM_LOG);
    cudaFuncSetAttribute(k_pool_mma, cudaFuncAttributeMaxDynamicSharedMemorySize,
                         SM_TOTAL);
    k_w<<<24, 128>>>(U, Vw, Vb);
    k_logits<<<dim3(HW_ / NT, B_), 256, SMEM_LOG>>>(x, S, T);
    k_pool_mma<<<dim3(C_ / CTILE, B_, 3), 256, SM_TOTAL>>>(x, S, T);
}

// round 15
// speedup vs baseline: 1.2156x; 1.2156x over previous
#include <cuda_runtime.h>
#include <cuda_bf16.h>
#include <cstdint>

#define B_   32
#define C_   384
#define HW_  4096
#define M_   64
#define R_   16

typedef unsigned long long ull;

// scratch: W = U*Vw split to bf16 hi/lo, bL = U*Vb
__device__ __nv_bfloat16 g_Whi[M_ * C_];
__device__ __nv_bfloat16 g_Wlo[M_ * C_];
__device__ float         g_bL[M_];

// ---------------- common helpers ----------------
__device__ __forceinline__ uint32_t smem_u32(const void* p) {
    uint32_t a;
    asm("{ .reg .u64 t; cvta.to.shared.u64 t, %1; cvt.u32.u64 %0, t; }"
        : "=r"(a) : "l"(p));
    return a;
}
__device__ __forceinline__ uint32_t sw128(uint32_t off) {
    return off ^ ((off >> 3) & 0x70);
}
__device__ __forceinline__ void ldsm4(uint32_t* r, uint32_t addr) {
    asm volatile("ldmatrix.sync.aligned.m8n8.x4.shared.b16 {%0,%1,%2,%3}, [%4];"
        : "=r"(r[0]), "=r"(r[1]), "=r"(r[2]), "=r"(r[3]) : "r"(addr));
}
__device__ __forceinline__ void mma_bf16(float* d, const uint32_t* a,
                                         const uint32_t* b) {
    asm volatile(
        "mma.sync.aligned.m16n8k16.row.col.f32.bf16.bf16.f32 "
        "{%0,%1,%2,%3}, {%4,%5,%6,%7}, {%8,%9}, {%0,%1,%2,%3};"
        : "+f"(d[0]), "+f"(d[1]), "+f"(d[2]), "+f"(d[3])
        : "r"(a[0]), "r"(a[1]), "r"(a[2]), "r"(a[3]), "r"(b[0]), "r"(b[1]));
}

// ---------------- kernel 0: W = U Vw (fp32), split bf16; bL = U Vb --------
// grid 192 x 128: one c-value per thread.
__global__ void k_w(const float* __restrict__ U, const float* __restrict__ Vw,
                    const float* __restrict__ Vb)
{
    int g = blockIdx.x * 128 + threadIdx.x;       // 0..24575
    int m = g / C_;
    int c = g % C_;

    float acc = 0.0f;
#pragma unroll
    for (int r = 0; r < R_; r++) acc += U[m * R_ + r] * Vw[r * C_ + c];
    __nv_bfloat16 h = __float2bfloat16_rn(acc);
    float lo = acc - __bfloat162float(h);
    g_Whi[m * C_ + c] = h;
    g_Wlo[m * C_ + c] = __float2bfloat16_rn(lo);

    if (g < M_) {
        float a2 = 0.0f;
#pragma unroll
        for (int r = 0; r < R_; r++) a2 += U[g * R_ + r] * Vb[r];
        g_bL[g] = a2;
    }
}

// ---------------- kernel 1: L = W x + bL ; S = softmax_M(L) ---------------
// grid (16 n-tiles, 32 b), 256 threads (8 warps x 32 n each).
// W hi/lo resident in smem (padded rows 784B); x staged transposed via
// STS.128 (conflict-free under SW128). mma bf16 3-term; softmax via shfl.

#define NT    256                     // n per block
#define CCH   64                      // c per chunk
#define NCH   (C_ / CCH)              // 6

// smem byte offsets
#define SW_HI 0                       // W hi: 64 rows x 784B = 50176
#define SW_LO 50176
#define SX_HI 100352                  // x tile: 256 rows x 128B = 32768
#define SX_LO 133120
#define SBL   165888                  // 64 floats
#define SMEM_LOG 166144

__global__ __launch_bounds__(256, 1) void k_logits(
    const float* __restrict__ x, float* __restrict__ S, float* __restrict__ T)
{
    extern __shared__ char smem[];
    const uint32_t sb = smem_u32(smem);
    const int tid = threadIdx.x;
    const int w   = tid >> 5;
    const int l   = tid & 31;
    const int b   = blockIdx.y;
    const int n0  = blockIdx.x * NT;

    // fused zero of T: 512 blocks x 256 thr x 6 floats = 786432
    {
        int gt = (blockIdx.y * gridDim.x + blockIdx.x) * 256 + tid;
        float2* tz = (float2*)T + (size_t)gt * 3;
        float2 z = make_float2(0.0f, 0.0f);
        tz[0] = z; tz[1] = z; tz[2] = z;
    }

    // load W hi/lo into padded smem (row stride 392 bf16 = 784B)
    {
        __nv_bfloat16* whi = (__nv_bfloat16*)(smem + SW_HI);
        __nv_bfloat16* wlo = (__nv_bfloat16*)(smem + SW_LO);
        for (int i = tid; i < M_ * C_; i += 256) {
            int r = i / C_, c = i % C_;
            int d = r * 392 + c;
            whi[d] = g_Whi[i];
            wlo[d] = g_Wlo[i];
        }
    }
    if (tid < M_) ((float*)(smem + SBL))[tid] = g_bL[tid];

    // lane addressing
    const int arow = l & 15;
    const int acol = (l >> 4) << 4;               // bytes
    const int nrow = (l & 7) + ((l >> 4) << 3);
    const int bcol = ((l >> 3) & 1) << 4;         // bytes

    float acc[4][4][4];                           // [mt][j(n8)][reg]
#pragma unroll
    for (int mt = 0; mt < 4; mt++)
#pragma unroll
        for (int j = 0; j < 4; j++)
#pragma unroll
            for (int q = 0; q < 4; q++) acc[mt][j][q] = 0.0f;

    __syncthreads();

    const float* xb = x + (size_t)b * C_ * HW_ + n0 + tid;  // row n = tid

    for (int ch = 0; ch < NCH; ch++) {
        // stage x[chunk c's][256 n] transposed -> smem [n][c], SW128.
        // STS.128 per 8-c group: quarter-warp phases hit 8 distinct bank
        // groups (n%8 spreads via swizzle) -> conflict-free.
        __syncthreads();
        {
            const float* xp = xb + (size_t)(ch * CCH) * HW_;
            const uint32_t rowb = (uint32_t)tid * 128;
#pragma unroll
            for (int q = 0; q < 8; q++) {
                uint32_t hv[4], lv[4];
#pragma unroll
                for (int j = 0; j < 4; j++) {
                    float v0 = xp[(size_t)(q * 8 + 2 * j) * HW_];
                    float v1 = xp[(size_t)(q * 8 + 2 * j + 1) * HW_];
                    __nv_bfloat162 h = __floats2bfloat162_rn(v0, v1);
                    float r0 = v0 - __bfloat162float(h.x);
                    float r1 = v1 - __bfloat162float(h.y);
                    __nv_bfloat162 lo = __floats2bfloat162_rn(r0, r1);
                    hv[j] = *(uint32_t*)&h;
                    lv[j] = *(uint32_t*)&lo;
                }
                uint32_t sw = sw128(rowb + 16 * q);
                *(uint4*)(smem + SX_HI + sw) = make_uint4(hv[0], hv[1], hv[2], hv[3]);
                *(uint4*)(smem + SX_LO + sw) = make_uint4(lv[0], lv[1], lv[2], lv[3]);
            }
        }
        __syncthreads();

        // compute: 4 k-steps of 16 within chunk
#pragma unroll
        for (int s = 0; s < 4; s++) {
            uint32_t ah[4][4], al[4][4];
            const uint32_t acb = (uint32_t)(ch * 128 + 32 * s) + acol;
#pragma unroll
            for (int mt = 0; mt < 4; mt++) {
                uint32_t aa = (uint32_t)(16 * mt + arow) * 784 + acb;
                ldsm4(ah[mt], sb + SW_HI + aa);
                ldsm4(al[mt], sb + SW_LO + aa);
            }
            uint32_t bh[2][4], bl[2][4];
#pragma unroll
            for (int h = 0; h < 2; h++) {
                uint32_t ba = sw128((uint32_t)(32 * w + 16 * h + nrow) * 128
                                    + 32 * s + bcol);
                ldsm4(bh[h], sb + SX_HI + ba);
                ldsm4(bl[h], sb + SX_LO + ba);
            }
#pragma unroll
            for (int mt = 0; mt < 4; mt++)
#pragma unroll
                for (int h = 0; h < 2; h++) {
                    mma_bf16(acc[mt][2 * h],     ah[mt], bh[h]);
                    mma_bf16(acc[mt][2 * h],     ah[mt], bl[h]);
                    mma_bf16(acc[mt][2 * h],     al[mt], bh[h]);
                    mma_bf16(acc[mt][2 * h + 1], ah[mt], bh[h] + 2);
                    mma_bf16(acc[mt][2 * h + 1], ah[mt], bl[h] + 2);
                    mma_bf16(acc[mt][2 * h + 1], al[mt], bh[h] + 2);
                }
        }
    }

    // bias
    const int g  = l >> 2;
    const int tg = l & 3;
    {
        const float* sbl = (const float*)(smem + SBL);
#pragma unroll
        for (int mt = 0; mt < 4; mt++) {
            float b0 = sbl[16 * mt + g];
            float b1 = sbl[16 * mt + 8 + g];
#pragma unroll
            for (int j = 0; j < 4; j++) {
                acc[mt][j][0] += b0; acc[mt][j][1] += b0;
                acc[mt][j][2] += b1; acc[mt][j][3] += b1;
            }
        }
    }

    // softmax over m=64: 8 local + shfl over g-groups (xor 4,8,16)
#pragma unroll
    for (int j = 0; j < 4; j++)
#pragma unroll
        for (int col = 0; col < 2; col++) {
            float mx = -1e30f;
#pragma unroll
            for (int mt = 0; mt < 4; mt++)
                mx = fmaxf(mx, fmaxf(acc[mt][j][col], acc[mt][j][col + 2]));
            mx = fmaxf(mx, __shfl_xor_sync(0xffffffffu, mx, 4));
            mx = fmaxf(mx, __shfl_xor_sync(0xffffffffu, mx, 8));
            mx = fmaxf(mx, __shfl_xor_sync(0xffffffffu, mx, 16));
            float sum = 0.0f;
#pragma unroll
            for (int mt = 0; mt < 4; mt++) {
                float e0 = __expf(acc[mt][j][col] - mx);
                float e1 = __expf(acc[mt][j][col + 2] - mx);
                acc[mt][j][col] = e0; acc[mt][j][col + 2] = e1;
                sum += e0 + e1;
            }
            sum += __shfl_xor_sync(0xffffffffu, sum, 4);
            sum += __shfl_xor_sync(0xffffffffu, sum, 8);
            sum += __shfl_xor_sync(0xffffffffu, sum, 16);
            float inv = 1.0f / sum;
#pragma unroll
            for (int mt = 0; mt < 4; mt++) {
                acc[mt][j][col] *= inv; acc[mt][j][col + 2] *= inv;
            }
        }

    // store S[b][m][n]
    float* sp = S + (size_t)b * M_ * HW_ + n0 + 32 * w + 2 * tg;
#pragma unroll
    for (int mt = 0; mt < 4; mt++)
#pragma unroll
        for (int j = 0; j < 4; j++) {
            int r0 = 16 * mt + g;
            *(float2*)(sp + (size_t)r0 * HW_ + 8 * j) =
                make_float2(acc[mt][j][0], acc[mt][j][1]);
            *(float2*)(sp + (size_t)(r0 + 8) * HW_ + 8 * j) =
                make_float2(acc[mt][j][2], acc[mt][j][3]);
        }
}

// ================= pool kernel: warp-level bf16 mma.sync =================
// (round-9 proven version, unchanged)
// K-split 3 (grid.z): chunks 22/21/21, atomicAdd into zeroed T.

#define CTILE  128
#define KC     64

#define SM_AHI 0
#define SM_ALO 16384
#define SM_BHI 32768
#define SM_BLO 40960
#define SM_TOTAL 49152

__global__ __launch_bounds__(256, 1) void k_pool_mma(
    const float* __restrict__ x, const float* __restrict__ S,
    float* __restrict__ T)
{
    extern __shared__ char smem[];
    const uint32_t sb = smem_u32(smem);
    const int tid = threadIdx.x;
    const int w   = tid >> 5;
    const int l   = tid & 31;
    const int c0  = blockIdx.x * CTILE;
    const int b   = blockIdx.y;
    const int ks  = blockIdx.z;                   // 0..2

    const int start = (ks == 0) ? 0 : (22 + 21 * (ks - 1));
    const int cnt   = (ks == 0) ? 22 : 21;

    const float* xb = x + ((size_t)b * C_ + c0) * HW_;
    const float* Sb = S + (size_t)b * M_ * HW_;

    const int cp = tid & 31;
    const int r0 = tid >> 5;

    const int arow = 16 * w + (l & 15);
    const int acol = (l >> 4) * 16;
    const int nrow = (l & 7) + ((l >> 4) << 3);
    const int bcol = ((l >> 3) & 1) * 16;

    float acc[8][4];
#pragma unroll
    for (int j = 0; j < 8; j++)
#pragma unroll
        for (int q = 0; q < 4; q++) acc[j][q] = 0.0f;

    float2 av[16], bv[8];
    {
        const int k0 = start * KC;
#pragma unroll
        for (int i = 0; i < 16; i++)
            av[i] = *(const float2*)(xb + (size_t)(r0 + 8 * i) * HW_ + k0 + 2 * cp);
#pragma unroll
        for (int i = 0; i < 8; i++)
            bv[i] = *(const float2*)(Sb + (size_t)(r0 + 8 * i) * HW_ + k0 + 2 * cp);
    }

    for (int ci = 0; ci < cnt; ci++) {
#pragma unroll
        for (int i = 0; i < 16; i++) {
            uint32_t sw = sw128((r0 + 8 * i) * 128 + 4 * cp);
            __nv_bfloat162 h = __floats2bfloat162_rn(av[i].x, av[i].y);
            float rx = av[i].x - __bfloat162float(h.x);
            float ry = av[i].y - __bfloat162float(h.y);
            __nv_bfloat162 lo = __floats2bfloat162_rn(rx, ry);
            *(uint32_t*)(smem + SM_AHI + sw) = *(uint32_t*)&h;
            *(uint32_t*)(smem + SM_ALO + sw) = *(uint32_t*)&lo;
        }
#pragma unroll
        for (int i = 0; i < 8; i++) {
            uint32_t sw = sw128((r0 + 8 * i) * 128 + 4 * cp);
            __nv_bfloat162 h = __floats2bfloat162_rn(bv[i].x, bv[i].y);
            float rx = bv[i].x - __bfloat162float(h.x);
            float ry = bv[i].y - __bfloat162float(h.y);
            __nv_bfloat162 lo = __floats2bfloat162_rn(rx, ry);
            *(uint32_t*)(smem + SM_BHI + sw) = *(uint32_t*)&h;
            *(uint32_t*)(smem + SM_BLO + sw) = *(uint32_t*)&lo;
        }
        __syncthreads();

        if (ci + 1 < cnt) {
            const int k1 = (start + ci + 1) * KC;
#pragma unroll
            for (int i = 0; i < 16; i++)
                av[i] = *(const float2*)(xb + (size_t)(r0 + 8 * i) * HW_ + k1 + 2 * cp);
#pragma unroll
            for (int i = 0; i < 8; i++)
                bv[i] = *(const float2*)(Sb + (size_t)(r0 + 8 * i) * HW_ + k1 + 2 * cp);
        }

#pragma unroll
        for (int s = 0; s < 4; s++) {
            uint32_t ah[4], al[4];
            uint32_t asw = sw128(arow * 128 + 32 * s + acol);
            ldsm4(ah, sb + SM_AHI + asw);
            ldsm4(al, sb + SM_ALO + asw);
#pragma unroll
            for (int jp = 0; jp < 4; jp++) {
                uint32_t bh[4], bl[4];
                uint32_t bsw = sw128((16 * jp + nrow) * 128 + 32 * s + bcol);
                ldsm4(bh, sb + SM_BHI + bsw);
                ldsm4(bl, sb + SM_BLO + bsw);
                mma_bf16(acc[2 * jp],     ah, bh);
                mma_bf16(acc[2 * jp],     ah, bl);
                mma_bf16(acc[2 * jp],     al, bh);
                mma_bf16(acc[2 * jp + 1], ah, bh + 2);
                mma_bf16(acc[2 * jp + 1], ah, bl + 2);
                mma_bf16(acc[2 * jp + 1], al, bh + 2);
            }
        }
        __syncthreads();
    }

    const int g  = l >> 2;
    const int q2 = (l & 3) * 2;
    float* tb = T + ((size_t)b * C_ + c0 + 16 * w) * M_;
#pragma unroll
    for (int j = 0; j < 8; j++) {
        atomicAdd(tb + (size_t)g * M_ + 8 * j + q2,           acc[j][0]);
        atomicAdd(tb + (size_t)g * M_ + 8 * j + q2 + 1,       acc[j][1]);
        atomicAdd(tb + (size_t)(g + 8) * M_ + 8 * j + q2,     acc[j][2]);
        atomicAdd(tb + (size_t)(g + 8) * M_ + 8 * j + q2 + 1, acc[j][3]);
    }
}

// ---------------- launch ----------------
extern "C" void kernel_launch(void* const* d_in, const int* in_sizes, int n_in,
                              void* d_out, int out_size)
{
    const float* x  = (const float*)d_in[0];
    const float* Vw = (const float*)d_in[1];
    const float* Vb = (const float*)d_in[2];
    const float* U  = (const float*)d_in[3];

    float* out = (float*)d_out;
    float* T = out;                           // [B, C, M]
    float* S = out + (size_t)B_ * C_ * M_;    // [B, M, N]

    cudaFuncSetAttribute(k_logits, cudaFuncAttributeMaxDynamicSharedMemorySize,
                         SMEM_LOG);
    cudaFuncSetAttribute(k_pool_mma, cudaFuncAttributeMaxDynamicSharedMemorySize,
                         SM_TOTAL);
    k_w<<<192, 128>>>(U, Vw, Vb);
    k_logits<<<dim3(HW_ / NT, B_), 256, SMEM_LOG>>>(x, S, T);
    k_pool_mma<<<dim3(C_ / CTILE, B_, 3), 256, SM_TOTAL>>>(x, S, T);
}

// round 16
// speedup vs baseline: 1.3107x; 1.0782x over previous
#include <cuda_runtime.h>
#include <cuda_bf16.h>
#include <cstdint>

#define B_   32
#define C_   384
#define HW_  4096
#define M_   64
#define R_   16

typedef unsigned long long ull;

// scratch: W = U*Vw split to bf16 hi/lo, bL = U*Vb
__device__ __nv_bfloat16 g_Whi[M_ * C_];
__device__ __nv_bfloat16 g_Wlo[M_ * C_];
__device__ float         g_bL[M_];

// ---------------- common helpers ----------------
__device__ __forceinline__ uint32_t smem_u32(const void* p) {
    uint32_t a;
    asm("{ .reg .u64 t; cvta.to.shared.u64 t, %1; cvt.u32.u64 %0, t; }"
        : "=r"(a) : "l"(p));
    return a;
}
__device__ __forceinline__ uint32_t sw128(uint32_t off) {
    return off ^ ((off >> 3) & 0x70);
}
__device__ __forceinline__ void ldsm4(uint32_t* r, uint32_t addr) {
    asm volatile("ldmatrix.sync.aligned.m8n8.x4.shared.b16 {%0,%1,%2,%3}, [%4];"
        : "=r"(r[0]), "=r"(r[1]), "=r"(r[2]), "=r"(r[3]) : "r"(addr));
}
__device__ __forceinline__ void mma_bf16(float* d, const uint32_t* a,
                                         const uint32_t* b) {
    asm volatile(
        "mma.sync.aligned.m16n8k16.row.col.f32.bf16.bf16.f32 "
        "{%0,%1,%2,%3}, {%4,%5,%6,%7}, {%8,%9}, {%0,%1,%2,%3};"
        : "+f"(d[0]), "+f"(d[1]), "+f"(d[2]), "+f"(d[3])
        : "r"(a[0]), "r"(a[1]), "r"(a[2]), "r"(a[3]), "r"(b[0]), "r"(b[1]));
}

// ---------------- kernel 0: W = U Vw (fp32), split bf16; bL = U Vb --------
// grid 192 x 128: one c-value per thread.
__global__ void k_w(const float* __restrict__ U, const float* __restrict__ Vw,
                    const float* __restrict__ Vb)
{
    int g = blockIdx.x * 128 + threadIdx.x;       // 0..24575
    int m = g / C_;
    int c = g % C_;

    float acc = 0.0f;
#pragma unroll
    for (int r = 0; r < R_; r++) acc += U[m * R_ + r] * Vw[r * C_ + c];
    __nv_bfloat16 h = __float2bfloat16_rn(acc);
    float lo = acc - __bfloat162float(h);
    g_Whi[m * C_ + c] = h;
    g_Wlo[m * C_ + c] = __float2bfloat16_rn(lo);

    if (g < M_) {
        float a2 = 0.0f;
#pragma unroll
        for (int r = 0; r < R_; r++) a2 += U[g * R_ + r] * Vb[r];
        g_bL[g] = a2;
    }
}

// ---------------- kernel 1: L = W x + bL ; S = softmax_M(L) ---------------
// grid (16 n-tiles, 32 b), 256 threads (8 warps x 32 n each).
// W hi/lo resident in smem; x PREFETCHED to regs for chunk ch+1 during
// chunk ch's compute (pool-kernel pattern), staged via STS.128 under SW128.

#define NT    256                     // n per block
#define CCH   64                      // c per chunk
#define NCH   (C_ / CCH)              // 6

// smem byte offsets
#define SW_HI 0                       // W hi: 64 rows x 784B = 50176
#define SW_LO 50176
#define SX_HI 100352                  // x tile: 256 rows x 128B = 32768
#define SX_LO 133120
#define SBL   165888                  // 64 floats
#define SMEM_LOG 166144

__global__ __launch_bounds__(256, 1) void k_logits(
    const float* __restrict__ x, float* __restrict__ S, float* __restrict__ T)
{
    extern __shared__ char smem[];
    const uint32_t sb = smem_u32(smem);
    const int tid = threadIdx.x;
    const int w   = tid >> 5;
    const int l   = tid & 31;
    const int b   = blockIdx.y;
    const int n0  = blockIdx.x * NT;

    // fused zero of T: 512 blocks x 256 thr x 6 floats = 786432
    {
        int gt = (blockIdx.y * gridDim.x + blockIdx.x) * 256 + tid;
        float2* tz = (float2*)T + (size_t)gt * 3;
        float2 z = make_float2(0.0f, 0.0f);
        tz[0] = z; tz[1] = z; tz[2] = z;
    }

    // load W hi/lo into padded smem (row stride 392 bf16 = 784B)
    {
        __nv_bfloat16* whi = (__nv_bfloat16*)(smem + SW_HI);
        __nv_bfloat16* wlo = (__nv_bfloat16*)(smem + SW_LO);
        for (int i = tid; i < M_ * C_; i += 256) {
            int r = i / C_, c = i % C_;
            int d = r * 392 + c;
            whi[d] = g_Whi[i];
            wlo[d] = g_Wlo[i];
        }
    }
    if (tid < M_) ((float*)(smem + SBL))[tid] = g_bL[tid];

    // lane addressing
    const int arow = l & 15;
    const int acol = (l >> 4) << 4;               // bytes
    const int nrow = (l & 7) + ((l >> 4) << 3);
    const int bcol = ((l >> 3) & 1) << 4;         // bytes

    float acc[4][4][4];                           // [mt][j(n8)][reg]
#pragma unroll
    for (int mt = 0; mt < 4; mt++)
#pragma unroll
        for (int j = 0; j < 4; j++)
#pragma unroll
            for (int q = 0; q < 4; q++) acc[mt][j][q] = 0.0f;

    const float* xb = x + (size_t)b * C_ * HW_ + n0 + tid;  // row n = tid

    // prefetch chunk 0
    float pv[CCH];
#pragma unroll
    for (int c = 0; c < CCH; c++) pv[c] = xb[(size_t)c * HW_];

    __syncthreads();

    for (int ch = 0; ch < NCH; ch++) {
        if (ch > 0) __syncthreads();   // prev compute done reading tile

        // convert prefetched regs -> bf16 hi/lo, STS.128 into SW128 tile
        {
            const uint32_t rowb = (uint32_t)tid * 128;
#pragma unroll
            for (int q = 0; q < 8; q++) {
                uint32_t hv[4], lv[4];
#pragma unroll
                for (int j = 0; j < 4; j++) {
                    float v0 = pv[q * 8 + 2 * j];
                    float v1 = pv[q * 8 + 2 * j + 1];
                    __nv_bfloat162 h = __floats2bfloat162_rn(v0, v1);
                    float r0 = v0 - __bfloat162float(h.x);
                    float r1 = v1 - __bfloat162float(h.y);
                    __nv_bfloat162 lo = __floats2bfloat162_rn(r0, r1);
                    hv[j] = *(uint32_t*)&h;
                    lv[j] = *(uint32_t*)&lo;
                }
                uint32_t sw = sw128(rowb + 16 * q);
                *(uint4*)(smem + SX_HI + sw) = make_uint4(hv[0], hv[1], hv[2], hv[3]);
                *(uint4*)(smem + SX_LO + sw) = make_uint4(lv[0], lv[1], lv[2], lv[3]);
            }
        }
        __syncthreads();

        // prefetch next chunk (loads land during compute below)
        if (ch + 1 < NCH) {
            const float* xp = xb + (size_t)((ch + 1) * CCH) * HW_;
#pragma unroll
            for (int c = 0; c < CCH; c++) pv[c] = xp[(size_t)c * HW_];
        }

        // compute: 4 k-steps of 16 within chunk
#pragma unroll
        for (int s = 0; s < 4; s++) {
            uint32_t ah[4][4], al[4][4];
            const uint32_t acb = (uint32_t)(ch * 128 + 32 * s) + acol;
#pragma unroll
            for (int mt = 0; mt < 4; mt++) {
                uint32_t aa = (uint32_t)(16 * mt + arow) * 784 + acb;
                ldsm4(ah[mt], sb + SW_HI + aa);
                ldsm4(al[mt], sb + SW_LO + aa);
            }
            uint32_t bh[2][4], bl[2][4];
#pragma unroll
            for (int h = 0; h < 2; h++) {
                uint32_t ba = sw128((uint32_t)(32 * w + 16 * h + nrow) * 128
                                    + 32 * s + bcol);
                ldsm4(bh[h], sb + SX_HI + ba);
                ldsm4(bl[h], sb + SX_LO + ba);
            }
#pragma unroll
            for (int mt = 0; mt < 4; mt++)
#pragma unroll
                for (int h = 0; h < 2; h++) {
                    mma_bf16(acc[mt][2 * h],     ah[mt], bh[h]);
                    mma_bf16(acc[mt][2 * h],     ah[mt], bl[h]);
                    mma_bf16(acc[mt][2 * h],     al[mt], bh[h]);
                    mma_bf16(acc[mt][2 * h + 1], ah[mt], bh[h] + 2);
                    mma_bf16(acc[mt][2 * h + 1], ah[mt], bl[h] + 2);
                    mma_bf16(acc[mt][2 * h + 1], al[mt], bh[h] + 2);
                }
        }
    }

    // bias
    const int g  = l >> 2;
    const int tg = l & 3;
    {
        const float* sbl = (const float*)(smem + SBL);
#pragma unroll
        for (int mt = 0; mt < 4; mt++) {
            float b0 = sbl[16 * mt + g];
            float b1 = sbl[16 * mt + 8 + g];
#pragma unroll
            for (int j = 0; j < 4; j++) {
                acc[mt][j][0] += b0; acc[mt][j][1] += b0;
                acc[mt][j][2] += b1; acc[mt][j][3] += b1;
            }
        }
    }

    // softmax over m=64: 8 local + shfl over g-groups (xor 4,8,16)
#pragma unroll
    for (int j = 0; j < 4; j++)
#pragma unroll
        for (int col = 0; col < 2; col++) {
            float mx = -1e30f;
#pragma unroll
            for (int mt = 0; mt < 4; mt++)
                mx = fmaxf(mx, fmaxf(acc[mt][j][col], acc[mt][j][col + 2]));
            mx = fmaxf(mx, __shfl_xor_sync(0xffffffffu, mx, 4));
            mx = fmaxf(mx, __shfl_xor_sync(0xffffffffu, mx, 8));
            mx = fmaxf(mx, __shfl_xor_sync(0xffffffffu, mx, 16));
            float sum = 0.0f;
#pragma unroll
            for (int mt = 0; mt < 4; mt++) {
                float e0 = __expf(acc[mt][j][col] - mx);
                float e1 = __expf(acc[mt][j][col + 2] - mx);
                acc[mt][j][col] = e0; acc[mt][j][col + 2] = e1;
                sum += e0 + e1;
            }
            sum += __shfl_xor_sync(0xffffffffu, sum, 4);
            sum += __shfl_xor_sync(0xffffffffu, sum, 8);
            sum += __shfl_xor_sync(0xffffffffu, sum, 16);
            float inv = 1.0f / sum;
#pragma unroll
            for (int mt = 0; mt < 4; mt++) {
                acc[mt][j][col] *= inv; acc[mt][j][col + 2] *= inv;
            }
        }

    // store S[b][m][n]
    float* sp = S + (size_t)b * M_ * HW_ + n0 + 32 * w + 2 * tg;
#pragma unroll
    for (int mt = 0; mt < 4; mt++)
#pragma unroll
        for (int j = 0; j < 4; j++) {
            int r0 = 16 * mt + g;
            *(float2*)(sp + (size_t)r0 * HW_ + 8 * j) =
                make_float2(acc[mt][j][0], acc[mt][j][1]);
            *(float2*)(sp + (size_t)(r0 + 8) * HW_ + 8 * j) =
                make_float2(acc[mt][j][2], acc[mt][j][3]);
        }
}

// ================= pool kernel: warp-level bf16 mma.sync =================
// (round-9 proven version, unchanged)
// K-split 3 (grid.z): chunks 22/21/21, atomicAdd into zeroed T.

#define CTILE  128
#define KC     64

#define SM_AHI 0
#define SM_ALO 16384
#define SM_BHI 32768
#define SM_BLO 40960
#define SM_TOTAL 49152

__global__ __launch_bounds__(256, 1) void k_pool_mma(
    const float* __restrict__ x, const float* __restrict__ S,
    float* __restrict__ T)
{
    extern __shared__ char smem[];
    const uint32_t sb = smem_u32(smem);
    const int tid = threadIdx.x;
    const int w   = tid >> 5;
    const int l   = tid & 31;
    const int c0  = blockIdx.x * CTILE;
    const int b   = blockIdx.y;
    const int ks  = blockIdx.z;                   // 0..2

    const int start = (ks == 0) ? 0 : (22 + 21 * (ks - 1));
    const int cnt   = (ks == 0) ? 22 : 21;

    const float* xb = x + ((size_t)b * C_ + c0) * HW_;
    const float* Sb = S + (size_t)b * M_ * HW_;

    const int cp = tid & 31;
    const int r0 = tid >> 5;

    const int arow = 16 * w + (l & 15);
    const int acol = (l >> 4) * 16;
    const int nrow = (l & 7) + ((l >> 4) << 3);
    const int bcol = ((l >> 3) & 1) * 16;

    float acc[8][4];
#pragma unroll
    for (int j = 0; j < 8; j++)
#pragma unroll
        for (int q = 0; q < 4; q++) acc[j][q] = 0.0f;

    float2 av[16], bv[8];
    {
        const int k0 = start * KC;
#pragma unroll
        for (int i = 0; i < 16; i++)
            av[i] = *(const float2*)(xb + (size_t)(r0 + 8 * i) * HW_ + k0 + 2 * cp);
#pragma unroll
        for (int i = 0; i < 8; i++)
            bv[i] = *(const float2*)(Sb + (size_t)(r0 + 8 * i) * HW_ + k0 + 2 * cp);
    }

    for (int ci = 0; ci < cnt; ci++) {
#pragma unroll
        for (int i = 0; i < 16; i++) {
            uint32_t sw = sw128((r0 + 8 * i) * 128 + 4 * cp);
            __nv_bfloat162 h = __floats2bfloat162_rn(av[i].x, av[i].y);
            float rx = av[i].x - __bfloat162float(h.x);
            float ry = av[i].y - __bfloat162float(h.y);
            __nv_bfloat162 lo = __floats2bfloat162_rn(rx, ry);
            *(uint32_t*)(smem + SM_AHI + sw) = *(uint32_t*)&h;
            *(uint32_t*)(smem + SM_ALO + sw) = *(uint32_t*)&lo;
        }
#pragma unroll
        for (int i = 0; i < 8; i++) {
            uint32_t sw = sw128((r0 + 8 * i) * 128 + 4 * cp);
            __nv_bfloat162 h = __floats2bfloat162_rn(bv[i].x, bv[i].y);
            float rx = bv[i].x - __bfloat162float(h.x);
            float ry = bv[i].y - __bfloat162float(h.y);
            __nv_bfloat162 lo = __floats2bfloat162_rn(rx, ry);
            *(uint32_t*)(smem + SM_BHI + sw) = *(uint32_t*)&h;
            *(uint32_t*)(smem + SM_BLO + sw) = *(uint32_t*)&lo;
        }
        __syncthreads();

        if (ci + 1 < cnt) {
            const int k1 = (start + ci + 1) * KC;
#pragma unroll
            for (int i = 0; i < 16; i++)
                av[i] = *(const float2*)(xb + (size_t)(r0 + 8 * i) * HW_ + k1 + 2 * cp);
#pragma unroll
            for (int i = 0; i < 8; i++)
                bv[i] = *(const float2*)(Sb + (size_t)(r0 + 8 * i) * HW_ + k1 + 2 * cp);
        }

#pragma unroll
        for (int s = 0; s < 4; s++) {
            uint32_t ah[4], al[4];
            uint32_t asw = sw128(arow * 128 + 32 * s + acol);
            ldsm4(ah, sb + SM_AHI + asw);
            ldsm4(al, sb + SM_ALO + asw);
#pragma unroll
            for (int jp = 0; jp < 4; jp++) {
                uint32_t bh[4], bl[4];
                uint32_t bsw = sw128((16 * jp + nrow) * 128 + 32 * s + bcol);
                ldsm4(bh, sb + SM_BHI + bsw);
                ldsm4(bl, sb + SM_BLO + bsw);
                mma_bf16(acc[2 * jp],     ah, bh);
                mma_bf16(acc[2 * jp],     ah, bl);
                mma_bf16(acc[2 * jp],     al, bh);
                mma_bf16(acc[2 * jp + 1], ah, bh + 2);
                mma_bf16(acc[2 * jp + 1], ah, bl + 2);
                mma_bf16(acc[2 * jp + 1], al, bh + 2);
            }
        }
        __syncthreads();
    }

    const int g  = l >> 2;
    const int q2 = (l & 3) * 2;
    float* tb = T + ((size_t)b * C_ + c0 + 16 * w) * M_;
#pragma unroll
    for (int j = 0; j < 8; j++) {
        atomicAdd(tb + (size_t)g * M_ + 8 * j + q2,           acc[j][0]);
        atomicAdd(tb + (size_t)g * M_ + 8 * j + q2 + 1,       acc[j][1]);
        atomicAdd(tb + (size_t)(g + 8) * M_ + 8 * j + q2,     acc[j][2]);
        atomicAdd(tb + (size_t)(g + 8) * M_ + 8 * j + q2 + 1, acc[j][3]);
    }
}

// ---------------- launch ----------------
extern "C" void kernel_launch(void* const* d_in, const int* in_sizes, int n_in,
                              void* d_out, int out_size)
{
    const float* x  = (const float*)d_in[0];
    const float* Vw = (const float*)d_in[1];
    const float* Vb = (const float*)d_in[2];
    const float* U  = (const float*)d_in[3];

    float* out = (float*)d_out;
    float* T = out;                           // [B, C, M]
    float* S = out + (size_t)B_ * C_ * M_;    // [B, M, N]

    cudaFuncSetAttribute(k_logits, cudaFuncAttributeMaxDynamicSharedMemorySize,
                         SMEM_LOG);
    cudaFuncSetAttribute(k_pool_mma, cudaFuncAttributeMaxDynamicSharedMemorySize,
                         SM_TOTAL);
    k_w<<<192, 128>>>(U, Vw, Vb);
    k_logits<<<dim3(HW_ / NT, B_), 256, SMEM_LOG>>>(x, S, T);
    k_pool_mma<<<dim3(C_ / CTILE, B_, 3), 256, SM_TOTAL>>>(x, S, T);
}